// round 3
// baseline (speedup 1.0000x reference)
#include <cuda_runtime.h>
#include <cstdint>

// Problem dims (fixed)
#define BB 2
#define SS 2048
#define DD 1024
#define HH 16
#define DHH 64
// M rows of the projection GEMMs
#define MM (BB*SS)   // 4096

// Scratch (allocation-free rule: __device__ globals)
__device__ float g_Q[BB*SS*DD];
__device__ float g_K[BB*SS*DD];
__device__ float g_V[BB*SS*DD];
__device__ float g_O[BB*SS*DD];

// ---------------------------------------------------------------------------
// GEMM: C = X @ W^T.  X:[M,K] row-major, W:[N,K] row-major (torch Linear).
// MODE 0: scatter output into head layout [B,H,S,DH]
// MODE 1: plain row-major [M,N]
// Tiles: 64x64 block, K-step 16, 256 threads, 4x4 per-thread micro-tile.
// ---------------------------------------------------------------------------
template<int MODE>
__global__ void __launch_bounds__(256)
gemm_xwT(const float* __restrict__ X, const float* __restrict__ W,
         float* __restrict__ C)
{
    const int K = DD;
    __shared__ __align__(16) float As[16][68];
    __shared__ __align__(16) float Bs[16][68];

    int tid = threadIdx.x;
    int tx = tid & 15;       // 0..15  -> 4 cols each
    int ty = tid >> 4;       // 0..15  -> 4 rows each
    int row0 = blockIdx.y * 64;
    int col0 = blockIdx.x * 64;

    int lm = tid >> 2;        // 0..63
    int lk = (tid & 3) << 2;  // 0,4,8,12
    const float* xp = X + (size_t)(row0 + lm) * K + lk;
    const float* wp = W + (size_t)(col0 + lm) * K + lk;

    float acc[4][4] = {};

    for (int k0 = 0; k0 < K; k0 += 16) {
        float4 xv = *(const float4*)(xp + k0);
        float4 wv = *(const float4*)(wp + k0);
        As[lk+0][lm] = xv.x; As[lk+1][lm] = xv.y;
        As[lk+2][lm] = xv.z; As[lk+3][lm] = xv.w;
        Bs[lk+0][lm] = wv.x; Bs[lk+1][lm] = wv.y;
        Bs[lk+2][lm] = wv.z; Bs[lk+3][lm] = wv.w;
        __syncthreads();
        #pragma unroll
        for (int kk = 0; kk < 16; ++kk) {
            float4 av = *(const float4*)&As[kk][ty << 2];
            float4 bv = *(const float4*)&Bs[kk][tx << 2];
            float a[4] = {av.x, av.y, av.z, av.w};
            float b[4] = {bv.x, bv.y, bv.z, bv.w};
            #pragma unroll
            for (int i = 0; i < 4; ++i)
                #pragma unroll
                for (int j = 0; j < 4; ++j)
                    acc[i][j] += a[i] * b[j];
        }
        __syncthreads();
    }

    #pragma unroll
    for (int i = 0; i < 4; ++i) {
        int m = row0 + (ty << 2) + i;
        #pragma unroll
        for (int j = 0; j < 4; ++j) {
            int n = col0 + (tx << 2) + j;
            float v = acc[i][j];
            if (MODE == 0) {
                int b_ = m >> 11;        // m / S
                int s_ = m & 2047;       // m % S
                int h_ = n >> 6;         // n / DH
                int d_ = n & 63;         // n % DH
                C[(size_t)(((b_ << 4) + h_) * SS + s_) * DHH + d_] = v;
            } else {
                C[(size_t)m * DD + n] = v;
            }
        }
    }
}

// ---------------------------------------------------------------------------
// Fused attention: per CTA = 8 query rows of one (b,h).
// Phase 1: scores = Qs @ K^T / 8  (K streamed through smem, transposed tile)
// Phase 2: mask + softmax per row (one warp per row), write attn to gmem
// Phase 3: out = probs @ V  (V streamed through smem)
// Dynamic smem: 8*2048 fp32 score strip (64 KB). Static: Q tile + K/V tile.
// ---------------------------------------------------------------------------
__global__ void __launch_bounds__(256)
attn_kernel(const int* __restrict__ mask, float* __restrict__ attn_out,
            int write_attn)
{
    extern __shared__ float sc[];               // [8][2048]
    __shared__ float Qs[8][64];
    __shared__ float KV[64][65];

    int tid = threadIdx.x;
    int bh  = blockIdx.y;                       // b*H + h
    int q0  = blockIdx.x * 8;

    const float* Qb = g_Q + (size_t)(bh * SS + q0) * DHH;
    const float* Kb = g_K + (size_t)bh * SS * DHH;
    const float* Vb = g_V + (size_t)bh * SS * DHH;

    // Load Q tile (8x64 contiguous floats)
    for (int e = tid; e < 8 * 64; e += 256)
        Qs[e >> 6][e & 63] = Qb[e];

    const float scale = 0.125f;                 // 1/sqrt(64)
    int q = tid >> 5;                           // 0..7 (query row)
    int l = tid & 31;                           // lane

    // Per-thread invariant indices for tile loads
    int ld_r  = (tid + 0) >> 4;                 // base row pattern (recomputed per i)
    (void)ld_r;

    // ---- Phase 1: scores ----
    for (int jt = 0; jt < SS / 64; ++jt) {
        const float* Kt = Kb + (size_t)jt * 64 * DHH;
        #pragma unroll
        for (int i = 0; i < 4; ++i) {
            int idx4 = tid + i * 256;           // 0..1023 float4s
            int r  = idx4 >> 4;                 // row in tile 0..63
            int c4 = (idx4 & 15) << 2;          // col 0..60
            float4 kv = *(const float4*)(Kt + r * 64 + c4);
            KV[c4 + 0][r] = kv.x; KV[c4 + 1][r] = kv.y;
            KV[c4 + 2][r] = kv.z; KV[c4 + 3][r] = kv.w;
        }
        __syncthreads();
        float a0 = 0.f, a1 = 0.f;
        #pragma unroll
        for (int k = 0; k < 64; ++k) {
            float qv = Qs[q][k];
            a0 += qv * KV[k][l];
            a1 += qv * KV[k][l + 32];
        }
        sc[q * SS + jt * 64 + l]      = a0 * scale;
        sc[q * SS + jt * 64 + l + 32] = a1 * scale;
        __syncthreads();
    }

    // ---- Phase 2: mask + softmax, one warp per row ----
    {
        int w  = tid >> 5;
        int qg = q0 + w;
        const int* mrow = mask + (size_t)qg * SS;
        float* srow = sc + w * SS;

        float mx = -3.4e38f;
        for (int j = l; j < SS; j += 32) {
            float s = srow[j];
            if (mrow[j] == 0) s = -1e34f;
            srow[j] = s;
            mx = fmaxf(mx, s);
        }
        #pragma unroll
        for (int o = 16; o; o >>= 1)
            mx = fmaxf(mx, __shfl_xor_sync(0xffffffffu, mx, o));

        float sum = 0.f;
        for (int j = l; j < SS; j += 32) {
            float e = __expf(srow[j] - mx);
            srow[j] = e;
            sum += e;
        }
        #pragma unroll
        for (int o = 16; o; o >>= 1)
            sum += __shfl_xor_sync(0xffffffffu, sum, o);
        float inv = 1.0f / sum;

        float* arow = attn_out + ((size_t)bh * SS + qg) * SS;
        if (write_attn) {
            for (int j = l; j < SS; j += 32) {
                float p = srow[j] * inv;
                srow[j] = p;
                arow[j] = p;
            }
        } else {
            for (int j = l; j < SS; j += 32)
                srow[j] *= inv;
        }
    }
    __syncthreads();

    // ---- Phase 3: out = probs @ V ----
    float o0 = 0.f, o1 = 0.f;
    for (int jt = 0; jt < SS / 64; ++jt) {
        const float* Vt = Vb + (size_t)jt * 64 * DHH;
        #pragma unroll
        for (int i = 0; i < 4; ++i) {
            int idx4 = tid + i * 256;
            int r  = idx4 >> 4;
            int c4 = (idx4 & 15) << 2;
            float4 vv = *(const float4*)(Vt + r * 64 + c4);
            KV[r][c4 + 0] = vv.x; KV[r][c4 + 1] = vv.y;
            KV[r][c4 + 2] = vv.z; KV[r][c4 + 3] = vv.w;
        }
        __syncthreads();
        const float* prow = sc + q * SS + jt * 64;
        #pragma unroll
        for (int jj = 0; jj < 64; ++jj) {
            float pv = prow[jj];
            o0 += pv * KV[jj][l];
            o1 += pv * KV[jj][l + 32];
        }
        __syncthreads();
    }

    // Write pre-Wo output back in [B,S,D] layout (heads re-interleaved)
    int b_ = bh >> 4;
    int h_ = bh & 15;
    int qg = q0 + q;
    float* op = g_O + ((size_t)(b_ * SS + qg)) * DD + h_ * DHH;
    op[l]      = o0;
    op[l + 32] = o1;
}

extern "C" void kernel_launch(void* const* d_in, const int* in_sizes, int n_in,
                              void* d_out, int out_size)
{
    const float* q    = (const float*)d_in[0];
    const float* k    = (const float*)d_in[1];
    const float* v    = (const float*)d_in[2];
    const int*   mask = (const int*)  d_in[3];
    const float* Wq   = (const float*)d_in[4];
    const float* Wk   = (const float*)d_in[5];
    const float* Wv   = (const float*)d_in[6];
    const float* Wo   = (const float*)d_in[7];
    float* out = (float*)d_out;

    float *gq, *gk, *gv, *go;
    cudaGetSymbolAddress((void**)&gq, g_Q);
    cudaGetSymbolAddress((void**)&gk, g_K);
    cudaGetSymbolAddress((void**)&gv, g_V);
    cudaGetSymbolAddress((void**)&go, g_O);

    dim3 blk(256);
    dim3 gridG(DD / 64, MM / 64);               // (16, 64)

    gemm_xwT<0><<<gridG, blk>>>(q, Wq, gq);
    gemm_xwT<0><<<gridG, blk>>>(k, Wk, gk);
    gemm_xwT<0><<<gridG, blk>>>(v, Wv, gv);

    const long out_elems  = (long)BB * SS * DD;           // 4194304
    int write_attn = (out_size > out_elems) ? 1 : 0;
    float* attn_out = out + out_elems;

    size_t smem = 8 * SS * sizeof(float);                 // 65536
    cudaFuncSetAttribute(attn_kernel,
                         cudaFuncAttributeMaxDynamicSharedMemorySize,
                         (int)smem);
    dim3 gridA(SS / 8, BB * HH);                          // (256, 32)
    attn_kernel<<<gridA, blk, smem>>>(mask, attn_out, write_attn);

    gemm_xwT<1><<<gridG, blk>>>(go, Wo, out);
}

// round 4
// speedup vs baseline: 1.9009x; 1.9009x over previous
#include <cuda_runtime.h>
#include <cstdint>

// Problem dims (fixed)
#define BB 2
#define SS 2048
#define DD 1024
#define HH 16
#define DHH 64
#define MM (BB*SS)   // 4096

// Scratch (allocation-free rule: __device__ globals)
__device__ float g_Q[BB*SS*DD];
__device__ float g_K[BB*SS*DD];
__device__ float g_V[BB*SS*DD];
__device__ float g_O[BB*SS*DD];

// ---------------------------------------------------------------------------
// tf32 helpers
// ---------------------------------------------------------------------------
__device__ __forceinline__ unsigned f2tf(float f) {
    unsigned u;
    asm("cvt.rna.tf32.f32 %0, %1;" : "=r"(u) : "f"(f));
    return u;
}

__device__ __forceinline__ void mma_tf32(float* c, const unsigned* a, const unsigned* b) {
    asm volatile(
        "mma.sync.aligned.m16n8k8.row.col.f32.tf32.tf32.f32 "
        "{%0,%1,%2,%3}, {%4,%5,%6,%7}, {%8,%9}, {%0,%1,%2,%3};"
        : "+f"(c[0]), "+f"(c[1]), "+f"(c[2]), "+f"(c[3])
        : "r"(a[0]), "r"(a[1]), "r"(a[2]), "r"(a[3]),
          "r"(b[0]), "r"(b[1]));
}

// ---------------------------------------------------------------------------
// Tensor-core GEMM: C = X @ W^T (tf32, fp32 accum).
// X:[M,1024] row-major, W:[N,1024] row-major. CTA tile 128x64, 8 warps (4x2),
// warp tile 32x32, k-step 32 (4 x m16n8k8).
// MODE 0: scatter output into head layout [B,H,S,DH].  MODE 1: row-major.
// ---------------------------------------------------------------------------
template<int MODE>
__global__ void __launch_bounds__(256, 2)
gemm_tc(const float* __restrict__ X, const float* __restrict__ W,
        float* __restrict__ C)
{
    __shared__ __align__(16) float Xs[128][36];
    __shared__ __align__(16) float Ws[64][36];

    int tid  = threadIdx.x;
    int lane = tid & 31;
    int wid  = tid >> 5;
    int wm = wid >> 1;          // 0..3
    int wn = wid & 1;           // 0..1
    int g  = lane >> 2;         // 0..7
    int tg = lane & 3;          // 0..3
    int row0 = blockIdx.y * 128;
    int col0 = blockIdx.x * 64;

    float acc[2][4][4];
    #pragma unroll
    for (int h = 0; h < 2; ++h)
        #pragma unroll
        for (int j = 0; j < 4; ++j)
            #pragma unroll
            for (int e = 0; e < 4; ++e) acc[h][j][e] = 0.f;

    for (int k0 = 0; k0 < DD; k0 += 32) {
        // Load X tile 128x32 (1024 float4, 4 per thread)
        #pragma unroll
        for (int it = 0; it < 4; ++it) {
            int idx = tid + it * 256;
            int r  = idx >> 3;
            int c4 = (idx & 7) << 2;
            float4 xv = *(const float4*)&X[(size_t)(row0 + r) * DD + k0 + c4];
            *(float4*)&Xs[r][c4] = xv;
        }
        // Load W tile 64x32 (512 float4, 2 per thread)
        #pragma unroll
        for (int it = 0; it < 2; ++it) {
            int idx = tid + it * 256;
            int r  = idx >> 3;
            int c4 = (idx & 7) << 2;
            float4 wv = *(const float4*)&W[(size_t)(col0 + r) * DD + k0 + c4];
            *(float4*)&Ws[r][c4] = wv;
        }
        __syncthreads();

        #pragma unroll
        for (int k8 = 0; k8 < 4; ++k8) {
            int kk = k8 * 8;
            unsigned a[2][4], b[4][2];
            #pragma unroll
            for (int h = 0; h < 2; ++h) {
                int r = wm * 32 + h * 16 + g;
                a[h][0] = f2tf(Xs[r][kk + tg]);
                a[h][1] = f2tf(Xs[r + 8][kk + tg]);
                a[h][2] = f2tf(Xs[r][kk + tg + 4]);
                a[h][3] = f2tf(Xs[r + 8][kk + tg + 4]);
            }
            #pragma unroll
            for (int j = 0; j < 4; ++j) {
                int n = wn * 32 + j * 8 + g;
                b[j][0] = f2tf(Ws[n][kk + tg]);
                b[j][1] = f2tf(Ws[n][kk + tg + 4]);
            }
            #pragma unroll
            for (int h = 0; h < 2; ++h)
                #pragma unroll
                for (int j = 0; j < 4; ++j)
                    mma_tf32(acc[h][j], a[h], b[j]);
        }
        __syncthreads();
    }

    // Epilogue
    #pragma unroll
    for (int h = 0; h < 2; ++h) {
        #pragma unroll
        for (int j = 0; j < 4; ++j) {
            int m0 = row0 + wm * 32 + h * 16 + g;
            int n0 = col0 + wn * 32 + j * 8 + 2 * tg;
            #pragma unroll
            for (int half = 0; half < 2; ++half) {
                int m = m0 + half * 8;
                float2 val;
                val.x = acc[h][j][half * 2 + 0];
                val.y = acc[h][j][half * 2 + 1];
                if (MODE == 0) {
                    int b_ = m >> 11;
                    int s_ = m & 2047;
                    int h_ = n0 >> 6;
                    int d_ = n0 & 63;
                    *(float2*)&C[(size_t)(((b_ << 4) + h_) * SS + s_) * DHH + d_] = val;
                } else {
                    *(float2*)&C[(size_t)m * DD + n0] = val;
                }
            }
        }
    }
}

// ---------------------------------------------------------------------------
// Fused attention, register-tiled. CTA = 16 query rows of one (b,h),
// 512 threads (16 warps).
// Phase 1: scores (8q x 1key per thread, float4 over dh). Key tile = 256.
// Phase 2: mask + softmax (one warp per row), write attn to gmem.
// Phase 3: out = probs @ V (8q x 4d per thread, 16-way key split + reduce).
// Dynamic smem layout (floats):
//   sc      [0,       32768)   16 x 2048 scores
//   union   [32768,   53312)   phase1: KV4T 16x257 float4 (16448 fl)
//                              phase3: V4 16x65 float4 (4160) + partial 32x512
//   Qs4     [53312,   54336)   16 x 16 float4
// Total 54336 floats = 217344 bytes.
// ---------------------------------------------------------------------------
#define SMEM_FLOATS 54336

__global__ void __launch_bounds__(512, 1)
attn_kernel(const int* __restrict__ mask, float* __restrict__ attn_out,
            int write_attn)
{
    extern __shared__ float smem[];
    float*  sc      = smem;                                   // [16][2048]
    float4* KV      = (float4*)(smem + 32768);                // [16][257]
    float4* V4      = (float4*)(smem + 32768);                // [16][65]
    float*  partial = smem + 32768 + 4160;                    // [32][512]
    float4* Qs4     = (float4*)(smem + 53312);                // [16][16]

    int tid = threadIdx.x;
    int bh  = blockIdx.y;
    int q0  = blockIdx.x * 16;

    const float*  Qb  = g_Q + (size_t)(bh * SS + q0) * DHH;
    const float4* Kb4 = (const float4*)(g_K + (size_t)bh * SS * DHH);
    const float4* Vb4 = (const float4*)(g_V + (size_t)bh * SS * DHH);

    // Load Q tile: 16 q x 16 float4
    if (tid < 256) {
        Qs4[tid] = ((const float4*)Qb)[tid];
    }

    const float scale = 0.125f;   // 1/sqrt(64)

    // ---- Phase 1: scores ----
    {
        int j  = tid & 255;       // key within tile
        int qh = tid >> 8;        // 0/1 -> q 0..7 or 8..15
        for (int tile = 0; tile < SS / 256; ++tile) {
            // Load K tile 256x64 as float4-col-major KV[c4][key], stride 257
            #pragma unroll
            for (int it = 0; it < 8; ++it) {
                int idx = tid + it * 512;
                int r  = idx >> 4;
                int c4 = idx & 15;
                KV[c4 * 257 + r] = Kb4[(size_t)(tile * 256 + r) * 16 + c4];
            }
            __syncthreads();

            float a0=0,a1=0,a2=0,a3=0,a4=0,a5=0,a6=0,a7=0;
            #pragma unroll
            for (int c4 = 0; c4 < 16; ++c4) {
                float4 kv = KV[c4 * 257 + j];
                const float4* qp = &Qs4[(qh * 8) * 16 + c4];
                float4 qv;
                qv = qp[0*16]; a0 += qv.x*kv.x + qv.y*kv.y + qv.z*kv.z + qv.w*kv.w;
                qv = qp[1*16]; a1 += qv.x*kv.x + qv.y*kv.y + qv.z*kv.z + qv.w*kv.w;
                qv = qp[2*16]; a2 += qv.x*kv.x + qv.y*kv.y + qv.z*kv.z + qv.w*kv.w;
                qv = qp[3*16]; a3 += qv.x*kv.x + qv.y*kv.y + qv.z*kv.z + qv.w*kv.w;
                qv = qp[4*16]; a4 += qv.x*kv.x + qv.y*kv.y + qv.z*kv.z + qv.w*kv.w;
                qv = qp[5*16]; a5 += qv.x*kv.x + qv.y*kv.y + qv.z*kv.z + qv.w*kv.w;
                qv = qp[6*16]; a6 += qv.x*kv.x + qv.y*kv.y + qv.z*kv.z + qv.w*kv.w;
                qv = qp[7*16]; a7 += qv.x*kv.x + qv.y*kv.y + qv.z*kv.z + qv.w*kv.w;
            }
            int base = tile * 256 + j;
            sc[(qh*8 + 0)*SS + base] = a0 * scale;
            sc[(qh*8 + 1)*SS + base] = a1 * scale;
            sc[(qh*8 + 2)*SS + base] = a2 * scale;
            sc[(qh*8 + 3)*SS + base] = a3 * scale;
            sc[(qh*8 + 4)*SS + base] = a4 * scale;
            sc[(qh*8 + 5)*SS + base] = a5 * scale;
            sc[(qh*8 + 6)*SS + base] = a6 * scale;
            sc[(qh*8 + 7)*SS + base] = a7 * scale;
            __syncthreads();
        }
    }

    // ---- Phase 2: mask + softmax (warp per row) ----
    {
        int w = tid >> 5;         // 0..15 -> query row
        int l = tid & 31;
        int qg = q0 + w;
        const int* mrow = mask + (size_t)qg * SS;
        float* srow = sc + w * SS;

        float mx = -3.4e38f;
        for (int j = l; j < SS; j += 32) {
            float s = srow[j];
            if (mrow[j] == 0) s = -1e34f;
            srow[j] = s;
            mx = fmaxf(mx, s);
        }
        #pragma unroll
        for (int o = 16; o; o >>= 1)
            mx = fmaxf(mx, __shfl_xor_sync(0xffffffffu, mx, o));

        float sum = 0.f;
        for (int j = l; j < SS; j += 32) {
            float e = __expf(srow[j] - mx);
            srow[j] = e;
            sum += e;
        }
        #pragma unroll
        for (int o = 16; o; o >>= 1)
            sum += __shfl_xor_sync(0xffffffffu, sum, o);
        float inv = 1.0f / sum;

        float* arow = attn_out + ((size_t)bh * SS + qg) * SS;
        if (write_attn) {
            for (int j = l; j < SS; j += 32) {
                float p = srow[j] * inv;
                srow[j] = p;
                arow[j] = p;
            }
        } else {
            for (int j = l; j < SS; j += 32)
                srow[j] *= inv;
        }
    }
    __syncthreads();

    // ---- Phase 3: out = probs @ V ----
    {
        int group = tid >> 4;     // 0..31
        int c4    = tid & 15;     // d4 column
        int qh    = group >> 4;   // 0/1
        int ksub  = group & 15;   // key subset

        float4 acc[8];
        #pragma unroll
        for (int i = 0; i < 8; ++i) acc[i] = make_float4(0.f, 0.f, 0.f, 0.f);

        for (int tile = 0; tile < SS / 64; ++tile) {
            // Load V tile 64x64 as float4-col-major V4[c4][key], stride 65
            #pragma unroll
            for (int it = 0; it < 2; ++it) {
                int idx = tid + it * 512;
                int r  = idx >> 4;
                int cc = idx & 15;
                V4[cc * 65 + r] = Vb4[(size_t)(tile * 64 + r) * 16 + cc];
            }
            __syncthreads();

            #pragma unroll
            for (int kk = 0; kk < 4; ++kk) {
                int k = kk * 16 + ksub;
                float4 vd = V4[c4 * 65 + k];
                const float* pp = &sc[(qh * 8) * SS + tile * 64 + k];
                #pragma unroll
                for (int i = 0; i < 8; ++i) {
                    float p = pp[i * SS];
                    acc[i].x += p * vd.x;
                    acc[i].y += p * vd.y;
                    acc[i].z += p * vd.z;
                    acc[i].w += p * vd.w;
                }
            }
            __syncthreads();
        }

        // Write partials: partial[group][i*64 + c4*4 .. +3]
        #pragma unroll
        for (int i = 0; i < 8; ++i)
            *(float4*)&partial[group * 512 + i * 64 + c4 * 4] = acc[i];
    }
    __syncthreads();

    // Reduce 16 key-subsets and write g_O
    {
        int b_ = bh >> 4;
        int h_ = bh & 15;
        #pragma unroll
        for (int rep = 0; rep < 2; ++rep) {
            int o = tid + rep * 512;
            int q = o >> 6;
            int d = o & 63;
            const float* pp = &partial[((q >> 3) * 16) * 512 + (q & 7) * 64 + d];
            float s = 0.f;
            #pragma unroll
            for (int su = 0; su < 16; ++su)
                s += pp[su * 512];
            g_O[((size_t)(b_ * SS + q0 + q)) * DD + h_ * DHH + d] = s;
        }
    }
}

extern "C" void kernel_launch(void* const* d_in, const int* in_sizes, int n_in,
                              void* d_out, int out_size)
{
    const float* q    = (const float*)d_in[0];
    const float* k    = (const float*)d_in[1];
    const float* v    = (const float*)d_in[2];
    const int*   mask = (const int*)  d_in[3];
    const float* Wq   = (const float*)d_in[4];
    const float* Wk   = (const float*)d_in[5];
    const float* Wv   = (const float*)d_in[6];
    const float* Wo   = (const float*)d_in[7];
    float* out = (float*)d_out;

    float *gq, *gk, *gv, *go;
    cudaGetSymbolAddress((void**)&gq, g_Q);
    cudaGetSymbolAddress((void**)&gk, g_K);
    cudaGetSymbolAddress((void**)&gv, g_V);
    cudaGetSymbolAddress((void**)&go, g_O);

    dim3 blkG(256);
    dim3 gridG(DD / 64, MM / 128);              // (16, 32)

    gemm_tc<0><<<gridG, blkG>>>(q, Wq, gq);
    gemm_tc<0><<<gridG, blkG>>>(k, Wk, gk);
    gemm_tc<0><<<gridG, blkG>>>(v, Wv, gv);

    const long out_elems = (long)BB * SS * DD;  // 4194304
    int write_attn = (out_size > out_elems) ? 1 : 0;
    float* attn_out = out + out_elems;

    size_t smem = SMEM_FLOATS * sizeof(float);  // 217344
    cudaFuncSetAttribute(attn_kernel,
                         cudaFuncAttributeMaxDynamicSharedMemorySize,
                         (int)smem);
    dim3 gridA(SS / 16, BB * HH);               // (128, 32)
    attn_kernel<<<gridA, 512, smem>>>(mask, attn_out, write_attn);

    gemm_tc<1><<<gridG, blkG>>>(go, Wo, out);
}

// round 6
// speedup vs baseline: 1.9325x; 1.0166x over previous
#include <cuda_runtime.h>
#include <cuda_bf16.h>
#include <cstdint>

// Problem dims (fixed)
#define BB 2
#define SS 2048
#define DD 1024
#define HH 16
#define DHH 64
#define MM (BB*SS)   // 4096

// Scratch (allocation-free rule: __device__ globals)
__device__ __nv_bfloat16 g_Qh[BB*SS*DD];
__device__ __nv_bfloat16 g_Ql[BB*SS*DD];
__device__ __nv_bfloat16 g_Kh[BB*SS*DD];
__device__ __nv_bfloat16 g_Kl[BB*SS*DD];
__device__ __nv_bfloat16 g_Vth[BB*SS*DD];   // [bh][d][key]
__device__ __nv_bfloat16 g_Vtl[BB*SS*DD];
__device__ float g_O[BB*SS*DD];

// ---------------------------------------------------------------------------
// helpers
// ---------------------------------------------------------------------------
__device__ __forceinline__ unsigned f2tf(float f) {
    unsigned u;
    asm("cvt.rna.tf32.f32 %0, %1;" : "=r"(u) : "f"(f));
    return u;
}

__device__ __forceinline__ void mma_tf32(float* c, const unsigned* a, const unsigned* b) {
    asm volatile(
        "mma.sync.aligned.m16n8k8.row.col.f32.tf32.tf32.f32 "
        "{%0,%1,%2,%3}, {%4,%5,%6,%7}, {%8,%9}, {%0,%1,%2,%3};"
        : "+f"(c[0]), "+f"(c[1]), "+f"(c[2]), "+f"(c[3])
        : "r"(a[0]), "r"(a[1]), "r"(a[2]), "r"(a[3]),
          "r"(b[0]), "r"(b[1]));
}

__device__ __forceinline__ void mma_bf16(float* c, const unsigned* a, const unsigned* b) {
    asm volatile(
        "mma.sync.aligned.m16n8k16.row.col.f32.bf16.bf16.f32 "
        "{%0,%1,%2,%3}, {%4,%5,%6,%7}, {%8,%9}, {%0,%1,%2,%3};"
        : "+f"(c[0]), "+f"(c[1]), "+f"(c[2]), "+f"(c[3])
        : "r"(a[0]), "r"(a[1]), "r"(a[2]), "r"(a[3]),
          "r"(b[0]), "r"(b[1]));
}

// split two floats into packed bf16x2 hi + lo (x ~ hi + lo, err ~2^-17)
__device__ __forceinline__ void split2f(float2 v, unsigned& hi, unsigned& lo) {
    __nv_bfloat162 h, l;
    h.x = __float2bfloat16_rn(v.x);
    h.y = __float2bfloat16_rn(v.y);
    l.x = __float2bfloat16_rn(v.x - __bfloat162float(h.x));
    l.y = __float2bfloat16_rn(v.y - __bfloat162float(h.y));
    hi = *(unsigned*)&h;
    lo = *(unsigned*)&l;
}

// ---------------------------------------------------------------------------
// Tensor-core GEMM: C = X @ W^T (tf32, fp32 accum). CTA tile 128x64, 8 warps.
// MODE 0: split-bf16 output, head layout [bh][s][dh]  (Q, K)
// MODE 3: split-bf16 output, transposed [bh][dh][s]   (V)
// MODE 1: fp32 row-major [M,N]                        (final)
// ---------------------------------------------------------------------------
template<int MODE>
__global__ void __launch_bounds__(256, 2)
gemm_tc(const float* __restrict__ X, const float* __restrict__ W,
        __nv_bfloat16* __restrict__ Chi, __nv_bfloat16* __restrict__ Clo,
        float* __restrict__ C32)
{
    __shared__ __align__(16) float Xs[128][36];
    __shared__ __align__(16) float Ws[64][36];

    int tid  = threadIdx.x;
    int lane = tid & 31;
    int wid  = tid >> 5;
    int wm = wid >> 1;
    int wn = wid & 1;
    int g  = lane >> 2;
    int tg = lane & 3;
    int row0 = blockIdx.y * 128;
    int col0 = blockIdx.x * 64;

    float acc[2][4][4];
    #pragma unroll
    for (int h = 0; h < 2; ++h)
        #pragma unroll
        for (int j = 0; j < 4; ++j)
            #pragma unroll
            for (int e = 0; e < 4; ++e) acc[h][j][e] = 0.f;

    for (int k0 = 0; k0 < DD; k0 += 32) {
        #pragma unroll
        for (int it = 0; it < 4; ++it) {
            int idx = tid + it * 256;
            int r  = idx >> 3;
            int c4 = (idx & 7) << 2;
            *(float4*)&Xs[r][c4] = *(const float4*)&X[(size_t)(row0 + r) * DD + k0 + c4];
        }
        #pragma unroll
        for (int it = 0; it < 2; ++it) {
            int idx = tid + it * 256;
            int r  = idx >> 3;
            int c4 = (idx & 7) << 2;
            *(float4*)&Ws[r][c4] = *(const float4*)&W[(size_t)(col0 + r) * DD + k0 + c4];
        }
        __syncthreads();

        #pragma unroll
        for (int k8 = 0; k8 < 4; ++k8) {
            int kk = k8 * 8;
            unsigned a[2][4], b[4][2];
            #pragma unroll
            for (int h = 0; h < 2; ++h) {
                int r = wm * 32 + h * 16 + g;
                a[h][0] = f2tf(Xs[r][kk + tg]);
                a[h][1] = f2tf(Xs[r + 8][kk + tg]);
                a[h][2] = f2tf(Xs[r][kk + tg + 4]);
                a[h][3] = f2tf(Xs[r + 8][kk + tg + 4]);
            }
            #pragma unroll
            for (int j = 0; j < 4; ++j) {
                int n = wn * 32 + j * 8 + g;
                b[j][0] = f2tf(Ws[n][kk + tg]);
                b[j][1] = f2tf(Ws[n][kk + tg + 4]);
            }
            #pragma unroll
            for (int h = 0; h < 2; ++h)
                #pragma unroll
                for (int j = 0; j < 4; ++j)
                    mma_tf32(acc[h][j], a[h], b[j]);
        }
        __syncthreads();
    }

    #pragma unroll
    for (int h = 0; h < 2; ++h) {
        #pragma unroll
        for (int j = 0; j < 4; ++j) {
            int m0 = row0 + wm * 32 + h * 16 + g;
            int n0 = col0 + wn * 32 + j * 8 + 2 * tg;
            #pragma unroll
            for (int half = 0; half < 2; ++half) {
                int m = m0 + half * 8;
                float vx = acc[h][j][half * 2 + 0];
                float vy = acc[h][j][half * 2 + 1];
                if (MODE == 1) {
                    float2 val; val.x = vx; val.y = vy;
                    *(float2*)&C32[(size_t)m * DD + n0] = val;
                } else if (MODE == 0) {
                    int b_ = m >> 11, s_ = m & 2047;
                    int h_ = n0 >> 6, d_ = n0 & 63;
                    size_t base = ((size_t)(((b_ << 4) + h_) * SS + s_)) * DHH + d_;
                    __nv_bfloat162 hv, lv;
                    hv.x = __float2bfloat16_rn(vx);
                    hv.y = __float2bfloat16_rn(vy);
                    lv.x = __float2bfloat16_rn(vx - __bfloat162float(hv.x));
                    lv.y = __float2bfloat16_rn(vy - __bfloat162float(hv.y));
                    *(__nv_bfloat162*)&Chi[base] = hv;
                    *(__nv_bfloat162*)&Clo[base] = lv;
                } else {           // MODE 3: transposed V
                    int b_ = m >> 11, s_ = m & 2047;
                    #pragma unroll
                    for (int e = 0; e < 2; ++e) {
                        int d = n0 + e;
                        int h_ = d >> 6, dd = d & 63;
                        size_t base = ((size_t)(((b_ << 4) + h_) * DHH + dd)) * SS + s_;
                        float v = e ? vy : vx;
                        __nv_bfloat16 hb = __float2bfloat16_rn(v);
                        Chi[base] = hb;
                        Clo[base] = __float2bfloat16_rn(v - __bfloat162float(hb));
                    }
                }
            }
        }
    }
}

// ---------------------------------------------------------------------------
// Fused attention with bf16-split MMA. CTA = 16 q rows of one (b,h), 512 thr.
// smem: sc[16][2050] fp32 (131200 B) | sKh[256][72] bf16 (36864) at 131200
//       | sKl at 168064.  Phase 3 unions sVh[64][264] / sVl into K region.
// Total 204928 B.
// ---------------------------------------------------------------------------
#define SCS 2050
#define SMEM_ATTN 204928

__global__ void __launch_bounds__(512, 1)
attn_kernel(const int* __restrict__ mask, float* __restrict__ attn_out,
            int write_attn,
            const __nv_bfloat16* __restrict__ Qh, const __nv_bfloat16* __restrict__ Ql,
            const __nv_bfloat16* __restrict__ Kh, const __nv_bfloat16* __restrict__ Kl,
            const __nv_bfloat16* __restrict__ Vth, const __nv_bfloat16* __restrict__ Vtl,
            float* __restrict__ O)
{
    extern __shared__ float smem[];
    float* sc = smem;
    __nv_bfloat16* sKh = (__nv_bfloat16*)((char*)smem + 131200);
    __nv_bfloat16* sKl = (__nv_bfloat16*)((char*)smem + 168064);
    __nv_bfloat16* sVh = (__nv_bfloat16*)((char*)smem + 131200);
    __nv_bfloat16* sVl = (__nv_bfloat16*)((char*)smem + 164992);

    int tid  = threadIdx.x;
    int lane = tid & 31;
    int w    = tid >> 5;        // warp 0..15
    int g    = lane >> 2;       // 0..7
    int tg   = lane & 3;        // 0..3
    int bh   = blockIdx.y;
    int q0   = blockIdx.x * 16;

    // ---- Preload Q fragments (16 x 64, 4 k-steps) ----
    unsigned aQh[4][4], aQl[4][4];
    {
        const __nv_bfloat16* Qbh = Qh + ((size_t)(bh * SS + q0)) * DHH;
        const __nv_bfloat16* Qbl = Ql + ((size_t)(bh * SS + q0)) * DHH;
        #pragma unroll
        for (int ks = 0; ks < 4; ++ks) {
            #pragma unroll
            for (int j = 0; j < 4; ++j) {
                int r = g + ((j & 1) ? 8 : 0);
                int c = ks * 16 + 2 * tg + ((j >= 2) ? 8 : 0);
                aQh[ks][j] = *(const unsigned*)&Qbh[(size_t)r * DHH + c];
                aQl[ks][j] = *(const unsigned*)&Qbl[(size_t)r * DHH + c];
            }
        }
    }

    const float scale = 0.125f;   // 1/sqrt(64)

    // ---- Phase 1: scores = Q @ K^T (split bf16 MMA) ----
    {
        const __nv_bfloat16* Kbh = Kh + (size_t)bh * SS * DHH;
        const __nv_bfloat16* Kbl = Kl + (size_t)bh * SS * DHH;
        for (int t = 0; t < 8; ++t) {
            const uint4* srcH = (const uint4*)(Kbh + (size_t)t * 256 * DHH);
            const uint4* srcL = (const uint4*)(Kbl + (size_t)t * 256 * DHH);
            #pragma unroll
            for (int it = 0; it < 4; ++it) {
                int idx = tid + it * 512;     // 0..2047
                int key = idx >> 3;
                int c8  = idx & 7;
                *(uint4*)&sKh[key * 72 + c8 * 8] = srcH[idx];
                *(uint4*)&sKl[key * 72 + c8 * 8] = srcL[idx];
            }
            __syncthreads();

            #pragma unroll
            for (int nt = 0; nt < 2; ++nt) {
                int n0 = w * 16 + nt * 8;
                float c[4] = {0.f, 0.f, 0.f, 0.f};
                #pragma unroll
                for (int ks = 0; ks < 4; ++ks) {
                    int kcol = ks * 16 + 2 * tg;
                    unsigned bh0[2], bl0[2];
                    bh0[0] = *(unsigned*)&sKh[(n0 + g) * 72 + kcol];
                    bh0[1] = *(unsigned*)&sKh[(n0 + g) * 72 + kcol + 8];
                    bl0[0] = *(unsigned*)&sKl[(n0 + g) * 72 + kcol];
                    bl0[1] = *(unsigned*)&sKl[(n0 + g) * 72 + kcol + 8];
                    mma_bf16(c, aQh[ks], bh0);
                    mma_bf16(c, aQh[ks], bl0);
                    mma_bf16(c, aQl[ks], bh0);
                }
                int colb = t * 256 + n0 + 2 * tg;
                *(float2*)&sc[g * SCS + colb]       = make_float2(c[0] * scale, c[1] * scale);
                *(float2*)&sc[(g + 8) * SCS + colb] = make_float2(c[2] * scale, c[3] * scale);
            }
            __syncthreads();
        }
    }

    // ---- Phase 2: mask + softmax (warp per row) ----
    {
        int l  = lane;
        int qg = q0 + w;
        const int* mrow = mask + (size_t)qg * SS;
        float* srow = sc + w * SCS;

        float mx = -3.4e38f;
        for (int j = l; j < SS; j += 32) {
            float s = srow[j];
            if (mrow[j] == 0) s = -1e34f;
            srow[j] = s;
            mx = fmaxf(mx, s);
        }
        #pragma unroll
        for (int o = 16; o; o >>= 1)
            mx = fmaxf(mx, __shfl_xor_sync(0xffffffffu, mx, o));

        float sum = 0.f;
        for (int j = l; j < SS; j += 32) {
            float e = __expf(srow[j] - mx);
            srow[j] = e;
            sum += e;
        }
        #pragma unroll
        for (int o = 16; o; o >>= 1)
            sum += __shfl_xor_sync(0xffffffffu, sum, o);
        float inv = 1.0f / sum;

        float* arow = attn_out + ((size_t)bh * SS + qg) * SS;
        if (write_attn) {
            for (int j = l; j < SS; j += 32) {
                float p = srow[j] * inv;
                srow[j] = p;
                arow[j] = p;
            }
        } else {
            for (int j = l; j < SS; j += 32)
                srow[j] *= inv;
        }
    }
    __syncthreads();

    // ---- Phase 3: out = P @ V (split bf16 MMA, key-split across warps) ----
    {
        const __nv_bfloat16* Vbh = Vth + (size_t)bh * DHH * SS;
        const __nv_bfloat16* Vbl = Vtl + (size_t)bh * DHH * SS;

        float acc[8][4];
        #pragma unroll
        for (int i = 0; i < 8; ++i)
            #pragma unroll
            for (int e = 0; e < 4; ++e) acc[i][e] = 0.f;

        for (int t = 0; t < 8; ++t) {
            #pragma unroll
            for (int it = 0; it < 4; ++it) {
                int idx = tid + it * 512;    // 0..2047
                int d  = idx >> 5;
                int c8 = idx & 31;
                *(uint4*)&sVh[d * 264 + c8 * 8] =
                    *(const uint4*)&Vbh[(size_t)d * SS + t * 256 + c8 * 8];
                *(uint4*)&sVl[d * 264 + c8 * 8] =
                    *(const uint4*)&Vbl[(size_t)d * SS + t * 256 + c8 * 8];
            }
            __syncthreads();

            // A fragment: P rows g/g+8, keys (t*256 + w*16) + {2tg, 2tg+8}
            int kk = t * 256 + w * 16;
            unsigned pa_h[4], pa_l[4];
            split2f(*(float2*)&sc[g * SCS + kk + 2 * tg],           pa_h[0], pa_l[0]);
            split2f(*(float2*)&sc[(g + 8) * SCS + kk + 2 * tg],     pa_h[1], pa_l[1]);
            split2f(*(float2*)&sc[g * SCS + kk + 2 * tg + 8],       pa_h[2], pa_l[2]);
            split2f(*(float2*)&sc[(g + 8) * SCS + kk + 2 * tg + 8], pa_h[3], pa_l[3]);

            #pragma unroll
            for (int nt = 0; nt < 8; ++nt) {
                int n0  = nt * 8;
                int col = w * 16 + 2 * tg;
                unsigned bh0[2], bl0[2];
                bh0[0] = *(unsigned*)&sVh[(n0 + g) * 264 + col];
                bh0[1] = *(unsigned*)&sVh[(n0 + g) * 264 + col + 8];
                bl0[0] = *(unsigned*)&sVl[(n0 + g) * 264 + col];
                bl0[1] = *(unsigned*)&sVl[(n0 + g) * 264 + col + 8];
                mma_bf16(acc[nt], pa_h, bh0);
                mma_bf16(acc[nt], pa_h, bl0);
                mma_bf16(acc[nt], pa_l, bh0);
            }
            __syncthreads();
        }

        // Partials into sc (P no longer needed)
        float* partial = sc;
        #pragma unroll
        for (int nt = 0; nt < 8; ++nt) {
            int n0 = nt * 8;
            *(float2*)&partial[w * 1024 + g * 64 + n0 + 2 * tg] =
                make_float2(acc[nt][0], acc[nt][1]);
            *(float2*)&partial[w * 1024 + (g + 8) * 64 + n0 + 2 * tg] =
                make_float2(acc[nt][2], acc[nt][3]);
        }
    }
    __syncthreads();

    // ---- Reduce 16 warps' partials, write g_O ----
    {
        const float* partial = sc;
        int b_ = bh >> 4;
        int h_ = bh & 15;
        #pragma unroll
        for (int rep = 0; rep < 2; ++rep) {
            int o = tid + rep * 512;
            int q = o >> 6;
            int d = o & 63;
            float s = 0.f;
            #pragma unroll
            for (int ww = 0; ww < 16; ++ww)
                s += partial[ww * 1024 + o];
            O[((size_t)(b_ * SS + q0 + q)) * DD + h_ * DHH + d] = s;
        }
    }
}

extern "C" void kernel_launch(void* const* d_in, const int* in_sizes, int n_in,
                              void* d_out, int out_size)
{
    const float* q    = (const float*)d_in[0];
    const float* k    = (const float*)d_in[1];
    const float* v    = (const float*)d_in[2];
    const int*   mask = (const int*)  d_in[3];
    const float* Wq   = (const float*)d_in[4];
    const float* Wk   = (const float*)d_in[5];
    const float* Wv   = (const float*)d_in[6];
    const float* Wo   = (const float*)d_in[7];
    float* out = (float*)d_out;

    __nv_bfloat16 *qh, *ql, *kh, *kl, *vth, *vtl;
    float *go;
    cudaGetSymbolAddress((void**)&qh,  g_Qh);
    cudaGetSymbolAddress((void**)&ql,  g_Ql);
    cudaGetSymbolAddress((void**)&kh,  g_Kh);
    cudaGetSymbolAddress((void**)&kl,  g_Kl);
    cudaGetSymbolAddress((void**)&vth, g_Vth);
    cudaGetSymbolAddress((void**)&vtl, g_Vtl);
    cudaGetSymbolAddress((void**)&go,  g_O);

    dim3 blkG(256);
    dim3 gridG(DD / 64, MM / 128);              // (16, 32)

    gemm_tc<0><<<gridG, blkG>>>(q, Wq, qh, ql, nullptr);
    gemm_tc<0><<<gridG, blkG>>>(k, Wk, kh, kl, nullptr);
    gemm_tc<3><<<gridG, blkG>>>(v, Wv, vth, vtl, nullptr);

    const long out_elems = (long)BB * SS * DD;  // 4194304
    int write_attn = (out_size > out_elems) ? 1 : 0;
    float* attn_out = out + out_elems;

    cudaFuncSetAttribute(attn_kernel,
                         cudaFuncAttributeMaxDynamicSharedMemorySize,
                         SMEM_ATTN);
    dim3 gridA(SS / 16, BB * HH);               // (128, 32)
    attn_kernel<<<gridA, 512, SMEM_ATTN>>>(mask, attn_out, write_attn,
                                           qh, ql, kh, kl, vth, vtl, go);

    gemm_tc<1><<<gridG, blkG>>>(go, Wo, nullptr, nullptr, out);
}

// round 8
// speedup vs baseline: 2.8960x; 1.4986x over previous
#include <cuda_runtime.h>
#include <cuda_bf16.h>
#include <cstdint>

// Problem dims (fixed)
#define BB 2
#define SS 2048
#define DD 1024
#define HH 16
#define DHH 64
#define MM (BB*SS)   // 4096

// Scratch (allocation-free rule: __device__ globals)
__device__ __nv_bfloat16 g_Qh[BB*SS*DD];
__device__ __nv_bfloat16 g_Ql[BB*SS*DD];
__device__ __nv_bfloat16 g_Kh[BB*SS*DD];
__device__ __nv_bfloat16 g_Kl[BB*SS*DD];
__device__ __nv_bfloat16 g_Vth[BB*SS*DD];   // [bh][d][key]
__device__ __nv_bfloat16 g_Vtl[BB*SS*DD];
__device__ float g_O[BB*SS*DD];

// ---------------------------------------------------------------------------
// helpers
// ---------------------------------------------------------------------------
__device__ __forceinline__ unsigned f2tf(float f) {
    unsigned u;
    asm("cvt.rna.tf32.f32 %0, %1;" : "=r"(u) : "f"(f));
    return u;
}

__device__ __forceinline__ void mma_tf32(float* c, const unsigned* a, const unsigned* b) {
    asm volatile(
        "mma.sync.aligned.m16n8k8.row.col.f32.tf32.tf32.f32 "
        "{%0,%1,%2,%3}, {%4,%5,%6,%7}, {%8,%9}, {%0,%1,%2,%3};"
        : "+f"(c[0]), "+f"(c[1]), "+f"(c[2]), "+f"(c[3])
        : "r"(a[0]), "r"(a[1]), "r"(a[2]), "r"(a[3]),
          "r"(b[0]), "r"(b[1]));
}

__device__ __forceinline__ void mma_bf16(float* c, const unsigned* a, const unsigned* b) {
    asm volatile(
        "mma.sync.aligned.m16n8k16.row.col.f32.bf16.bf16.f32 "
        "{%0,%1,%2,%3}, {%4,%5,%6,%7}, {%8,%9}, {%0,%1,%2,%3};"
        : "+f"(c[0]), "+f"(c[1]), "+f"(c[2]), "+f"(c[3])
        : "r"(a[0]), "r"(a[1]), "r"(a[2]), "r"(a[3]),
          "r"(b[0]), "r"(b[1]));
}

__device__ __forceinline__ void split2f(float2 v, unsigned& hi, unsigned& lo) {
    __nv_bfloat162 h, l;
    h.x = __float2bfloat16_rn(v.x);
    h.y = __float2bfloat16_rn(v.y);
    l.x = __float2bfloat16_rn(v.x - __bfloat162float(h.x));
    l.y = __float2bfloat16_rn(v.y - __bfloat162float(h.y));
    hi = *(unsigned*)&h;
    lo = *(unsigned*)&l;
}

__device__ __forceinline__ void cpasync16(void* dst, const void* src) {
    unsigned d = (unsigned)__cvta_generic_to_shared(dst);
    asm volatile("cp.async.cg.shared.global [%0], [%1], 16;" :: "r"(d), "l"(src));
}
__device__ __forceinline__ void cp_commit() {
    asm volatile("cp.async.commit_group;");
}
template<int N> __device__ __forceinline__ void cp_wait() {
    asm volatile("cp.async.wait_group %0;" :: "n"(N));
}

__device__ __forceinline__ void ldmx4(unsigned& r0, unsigned& r1, unsigned& r2, unsigned& r3,
                                      const void* p) {
    unsigned a = (unsigned)__cvta_generic_to_shared(p);
    asm volatile("ldmatrix.sync.aligned.m8n8.x4.shared.b16 {%0,%1,%2,%3}, [%4];"
                 : "=r"(r0), "=r"(r1), "=r"(r2), "=r"(r3) : "r"(a));
}
__device__ __forceinline__ void ldmx2(unsigned& r0, unsigned& r1, const void* p) {
    unsigned a = (unsigned)__cvta_generic_to_shared(p);
    asm volatile("ldmatrix.sync.aligned.m8n8.x2.shared.b16 {%0,%1}, [%2];"
                 : "=r"(r0), "=r"(r1) : "r"(a));
}

// ---------------------------------------------------------------------------
// Tensor-core GEMM: C = X @ W^T (tf32, fp32 accum). CTA tile 128x64, 8 warps.
// MODE 0: split-bf16 output, head layout [bh][s][dh]  (Q, K)
// MODE 3: split-bf16 output, transposed [bh][dh][s]   (V)
// MODE 1: fp32 row-major [M,N]                        (final)
// ---------------------------------------------------------------------------
template<int MODE>
__global__ void __launch_bounds__(256, 2)
gemm_tc(const float* __restrict__ X, const float* __restrict__ W,
        __nv_bfloat16* __restrict__ Chi, __nv_bfloat16* __restrict__ Clo,
        float* __restrict__ C32)
{
    __shared__ __align__(16) float Xs[128][36];
    __shared__ __align__(16) float Ws[64][36];

    int tid  = threadIdx.x;
    int lane = tid & 31;
    int wid  = tid >> 5;
    int wm = wid >> 1;
    int wn = wid & 1;
    int g  = lane >> 2;
    int tg = lane & 3;
    int row0 = blockIdx.y * 128;
    int col0 = blockIdx.x * 64;

    float acc[2][4][4];
    #pragma unroll
    for (int h = 0; h < 2; ++h)
        #pragma unroll
        for (int j = 0; j < 4; ++j)
            #pragma unroll
            for (int e = 0; e < 4; ++e) acc[h][j][e] = 0.f;

    for (int k0 = 0; k0 < DD; k0 += 32) {
        #pragma unroll
        for (int it = 0; it < 4; ++it) {
            int idx = tid + it * 256;
            int r  = idx >> 3;
            int c4 = (idx & 7) << 2;
            *(float4*)&Xs[r][c4] = *(const float4*)&X[(size_t)(row0 + r) * DD + k0 + c4];
        }
        #pragma unroll
        for (int it = 0; it < 2; ++it) {
            int idx = tid + it * 256;
            int r  = idx >> 3;
            int c4 = (idx & 7) << 2;
            *(float4*)&Ws[r][c4] = *(const float4*)&W[(size_t)(col0 + r) * DD + k0 + c4];
        }
        __syncthreads();

        #pragma unroll
        for (int k8 = 0; k8 < 4; ++k8) {
            int kk = k8 * 8;
            unsigned a[2][4], b[4][2];
            #pragma unroll
            for (int h = 0; h < 2; ++h) {
                int r = wm * 32 + h * 16 + g;
                a[h][0] = f2tf(Xs[r][kk + tg]);
                a[h][1] = f2tf(Xs[r + 8][kk + tg]);
                a[h][2] = f2tf(Xs[r][kk + tg + 4]);
                a[h][3] = f2tf(Xs[r + 8][kk + tg + 4]);
            }
            #pragma unroll
            for (int j = 0; j < 4; ++j) {
                int n = wn * 32 + j * 8 + g;
                b[j][0] = f2tf(Ws[n][kk + tg]);
                b[j][1] = f2tf(Ws[n][kk + tg + 4]);
            }
            #pragma unroll
            for (int h = 0; h < 2; ++h)
                #pragma unroll
                for (int j = 0; j < 4; ++j)
                    mma_tf32(acc[h][j], a[h], b[j]);
        }
        __syncthreads();
    }

    #pragma unroll
    for (int h = 0; h < 2; ++h) {
        #pragma unroll
        for (int j = 0; j < 4; ++j) {
            int m0 = row0 + wm * 32 + h * 16 + g;
            int n0 = col0 + wn * 32 + j * 8 + 2 * tg;
            #pragma unroll
            for (int half = 0; half < 2; ++half) {
                int m = m0 + half * 8;
                float vx = acc[h][j][half * 2 + 0];
                float vy = acc[h][j][half * 2 + 1];
                if (MODE == 1) {
                    float2 val; val.x = vx; val.y = vy;
                    *(float2*)&C32[(size_t)m * DD + n0] = val;
                } else if (MODE == 0) {
                    int b_ = m >> 11, s_ = m & 2047;
                    int h_ = n0 >> 6, d_ = n0 & 63;
                    size_t base = ((size_t)(((b_ << 4) + h_) * SS + s_)) * DHH + d_;
                    __nv_bfloat162 hv, lv;
                    hv.x = __float2bfloat16_rn(vx);
                    hv.y = __float2bfloat16_rn(vy);
                    lv.x = __float2bfloat16_rn(vx - __bfloat162float(hv.x));
                    lv.y = __float2bfloat16_rn(vy - __bfloat162float(hv.y));
                    *(__nv_bfloat162*)&Chi[base] = hv;
                    *(__nv_bfloat162*)&Clo[base] = lv;
                } else {           // MODE 3: transposed V
                    int b_ = m >> 11, s_ = m & 2047;
                    #pragma unroll
                    for (int e = 0; e < 2; ++e) {
                        int d = n0 + e;
                        int h_ = d >> 6, dd = d & 63;
                        size_t base = ((size_t)(((b_ << 4) + h_) * DHH + dd)) * SS + s_;
                        float v = e ? vy : vx;
                        __nv_bfloat16 hb = __float2bfloat16_rn(v);
                        Chi[base] = hb;
                        Clo[base] = __float2bfloat16_rn(v - __bfloat162float(hb));
                    }
                }
            }
        }
    }
}

// ---------------------------------------------------------------------------
// Fused attention: cp.async double-buffered 128-key tiles, ldmatrix
// B-fragments, fused mask/max, slim softmax, 8x2 phase-3 split.
// CTA = 16 q rows of one (b,h), 512 threads.
// Tail-wait fix: the final tile of each pipeline is itself the newest
// committed cp.async group, so the last iteration must wait_group 0.
// ---------------------------------------------------------------------------
#define SCS 2052
#define SMEM_ATTN 206144

__global__ void __launch_bounds__(512, 1)
attn_kernel(const int* __restrict__ mask, float* __restrict__ attn_out,
            int write_attn,
            const __nv_bfloat16* __restrict__ Qh, const __nv_bfloat16* __restrict__ Ql,
            const __nv_bfloat16* __restrict__ Kh, const __nv_bfloat16* __restrict__ Kl,
            const __nv_bfloat16* __restrict__ Vth, const __nv_bfloat16* __restrict__ Vtl,
            float* __restrict__ O)
{
    extern __shared__ float smem[];
    char* sbase = (char*)smem;
    float* sc   = smem;
    float* red  = (float*)(sbase + 205056);
    float* partial = (float*)(sbase + 131328);

    int tid  = threadIdx.x;
    int lane = tid & 31;
    int w    = tid >> 5;        // warp 0..15
    int g    = lane >> 2;       // 0..7
    int tg   = lane & 3;        // 0..3
    int bh   = blockIdx.y;
    int q0   = blockIdx.x * 16;

    const __nv_bfloat16* Kbh = Kh  + (size_t)bh * SS * DHH;
    const __nv_bfloat16* Kbl = Kl  + (size_t)bh * SS * DHH;
    const __nv_bfloat16* Vbh = Vth + (size_t)bh * DHH * SS;
    const __nv_bfloat16* Vbl = Vtl + (size_t)bh * DHH * SS;

    auto prefetchK = [&](int t) {
        char* buf = sbase + 131328 + (t & 1) * 36864;
        #pragma unroll
        for (int i = 0; i < 4; ++i) {
            int idx  = tid + i * 512;          // 0..2047
            int part = idx >> 10;              // 0 hi, 1 lo
            int r    = (idx >> 3) & 127;
            int c8   = idx & 7;
            const __nv_bfloat16* src = (part ? Kbl : Kbh)
                + ((size_t)(t * 128 + r)) * DHH + c8 * 8;
            cpasync16(buf + part * 18432 + r * 144 + c8 * 16, src);
        }
        cp_commit();
    };
    auto prefetchV = [&](int t) {
        char* buf = sbase + 131328 + (t & 1) * 34816;
        #pragma unroll
        for (int i = 0; i < 4; ++i) {
            int idx  = tid + i * 512;
            int part = idx >> 10;
            int d    = (idx >> 4) & 63;
            int c8   = idx & 15;
            const __nv_bfloat16* src = (part ? Vbl : Vbh)
                + (size_t)d * SS + t * 128 + c8 * 8;
            cpasync16(buf + part * 17408 + d * 272 + c8 * 16, src);
        }
        cp_commit();
    };

    prefetchK(0);
    prefetchK(1);

    // ---- Preload Q fragments (16 x 64, 4 k-steps), overlaps with cp.async ----
    unsigned aQh[4][4], aQl[4][4];
    {
        const __nv_bfloat16* Qbh = Qh + ((size_t)(bh * SS + q0)) * DHH;
        const __nv_bfloat16* Qbl = Ql + ((size_t)(bh * SS + q0)) * DHH;
        #pragma unroll
        for (int ks = 0; ks < 4; ++ks) {
            #pragma unroll
            for (int j = 0; j < 4; ++j) {
                int r = g + ((j & 1) ? 8 : 0);
                int c = ks * 16 + 2 * tg + ((j >= 2) ? 8 : 0);
                aQh[ks][j] = *(const unsigned*)&Qbh[(size_t)r * DHH + c];
                aQl[ks][j] = *(const unsigned*)&Qbl[(size_t)r * DHH + c];
            }
        }
    }

    const float scale = 0.125f;   // 1/sqrt(64)
    const int n0 = w * 8;         // phase-1 key group of this warp
    float mxA = -3.4e38f, mxB = -3.4e38f;

    // ---- Phase 1: scores = Q @ K^T, mask + running max fused ----
    for (int t = 0; t < 16; ++t) {
        if (t < 15) cp_wait<1>(); else cp_wait<0>();
        __syncthreads();

        const __nv_bfloat16* bKh = (const __nv_bfloat16*)(sbase + 131328 + (t & 1) * 36864);
        const __nv_bfloat16* bKl = (const __nv_bfloat16*)((char*)bKh + 18432);

        int li = lane & 7, lm = lane >> 3;
        unsigned kh[4][2], kl[4][2];
        ldmx4(kh[0][0], kh[0][1], kh[1][0], kh[1][1], bKh + (n0 + li) * 72 + lm * 8);
        ldmx4(kh[2][0], kh[2][1], kh[3][0], kh[3][1], bKh + (n0 + li) * 72 + 32 + lm * 8);
        ldmx4(kl[0][0], kl[0][1], kl[1][0], kl[1][1], bKl + (n0 + li) * 72 + lm * 8);
        ldmx4(kl[2][0], kl[2][1], kl[3][0], kl[3][1], bKl + (n0 + li) * 72 + 32 + lm * 8);

        float c[4] = {0.f, 0.f, 0.f, 0.f};
        #pragma unroll
        for (int ks = 0; ks < 4; ++ks) {
            mma_bf16(c, aQh[ks], kh[ks]);
            mma_bf16(c, aQh[ks], kl[ks]);
            mma_bf16(c, aQl[ks], kh[ks]);
        }
        __syncthreads();
        if (t + 2 < 16) prefetchK(t + 2);

        int col = t * 128 + n0 + 2 * tg;
        int2 mA = *(const int2*)&mask[(size_t)(q0 + g) * SS + col];
        int2 mB = *(const int2*)&mask[(size_t)(q0 + g + 8) * SS + col];
        float s0 = mA.x ? c[0] * scale : -1e34f;
        float s1 = mA.y ? c[1] * scale : -1e34f;
        float s2 = mB.x ? c[2] * scale : -1e34f;
        float s3 = mB.y ? c[3] * scale : -1e34f;
        mxA = fmaxf(mxA, fmaxf(s0, s1));
        mxB = fmaxf(mxB, fmaxf(s2, s3));
        *(float2*)&sc[g * SCS + col]       = make_float2(s0, s1);
        *(float2*)&sc[(g + 8) * SCS + col] = make_float2(s2, s3);
    }

    // quad-reduce max, store per-warp row maxes
    mxA = fmaxf(mxA, __shfl_xor_sync(0xffffffffu, mxA, 1));
    mxA = fmaxf(mxA, __shfl_xor_sync(0xffffffffu, mxA, 2));
    mxB = fmaxf(mxB, __shfl_xor_sync(0xffffffffu, mxB, 1));
    mxB = fmaxf(mxB, __shfl_xor_sync(0xffffffffu, mxB, 2));
    if (tg == 0) {
        red[g * 16 + w]       = mxA;
        red[(g + 8) * 16 + w] = mxB;
    }
    __syncthreads();

    // ---- prefetch V tiles 0,1 (overlaps softmax) ----
    prefetchV(0);
    prefetchV(1);

    // ---- Phase 2: softmax row w (one warp per row) ----
    {
        float mx = red[w * 16 + (lane & 15)];
        #pragma unroll
        for (int o = 8; o; o >>= 1)
            mx = fmaxf(mx, __shfl_xor_sync(0xffffffffu, mx, o));

        float* srow = sc + w * SCS;
        float sum = 0.f;
        #pragma unroll 4
        for (int j = lane * 4; j < SS; j += 128) {
            float4 sv = *(float4*)&srow[j];
            sv.x = __expf(sv.x - mx);
            sv.y = __expf(sv.y - mx);
            sv.z = __expf(sv.z - mx);
            sv.w = __expf(sv.w - mx);
            *(float4*)&srow[j] = sv;
            sum += sv.x + sv.y + sv.z + sv.w;
        }
        #pragma unroll
        for (int o = 16; o; o >>= 1)
            sum += __shfl_xor_sync(0xffffffffu, sum, o);
        float inv = 1.0f / sum;
        if (lane == 0) red[256 + w] = inv;
        __syncthreads();

        // normalized attn write (STG.128), sc keeps unnormalized exp
        if (write_attn) {
            float* arow = attn_out + ((size_t)bh * SS + q0 + w) * SS;
            #pragma unroll 4
            for (int j = lane * 4; j < SS; j += 128) {
                float4 sv = *(float4*)&srow[j];
                sv.x *= inv; sv.y *= inv; sv.z *= inv; sv.w *= inv;
                *(float4*)&arow[j] = sv;
            }
        }
    }

    float invA = red[256 + g];
    float invB = red[256 + g + 8];

    // ---- Phase 3: out = P @ V.  8-way key split x 2-way d split. ----
    {
        int kg  = w >> 1;             // key subgroup 0..7 (16 keys each)
        int dh2 = (w & 1) * 32;       // d half

        float acc[4][4];
        #pragma unroll
        for (int i = 0; i < 4; ++i)
            #pragma unroll
            for (int e = 0; e < 4; ++e) acc[i][e] = 0.f;

        int li = lane & 7, lm = (lane >> 3) & 1;

        for (int t = 0; t < 16; ++t) {
            if (t < 15) cp_wait<1>(); else cp_wait<0>();
            __syncthreads();

            const __nv_bfloat16* bVh = (const __nv_bfloat16*)(sbase + 131328 + (t & 1) * 34816);
            const __nv_bfloat16* bVl = (const __nv_bfloat16*)((char*)bVh + 17408);

            // A fragment: P rows g,g+8, keys t*128 + kg*16 + {2tg, 2tg+8}
            int kk = t * 128 + kg * 16;
            unsigned pa_h[4], pa_l[4];
            {
                float2 p0 = *(float2*)&sc[g * SCS + kk + 2 * tg];
                float2 p1 = *(float2*)&sc[(g + 8) * SCS + kk + 2 * tg];
                float2 p2 = *(float2*)&sc[g * SCS + kk + 2 * tg + 8];
                float2 p3 = *(float2*)&sc[(g + 8) * SCS + kk + 2 * tg + 8];
                p0.x *= invA; p0.y *= invA; p2.x *= invA; p2.y *= invA;
                p1.x *= invB; p1.y *= invB; p3.x *= invB; p3.y *= invB;
                split2f(p0, pa_h[0], pa_l[0]);
                split2f(p1, pa_h[1], pa_l[1]);
                split2f(p2, pa_h[2], pa_l[2]);
                split2f(p3, pa_h[3], pa_l[3]);
            }

            int kin = kg * 16;
            #pragma unroll
            for (int nt = 0; nt < 4; ++nt) {
                int nd = dh2 + nt * 8;
                unsigned bh0[2], bl0[2];
                ldmx2(bh0[0], bh0[1], bVh + (nd + li) * 136 + kin + lm * 8);
                ldmx2(bl0[0], bl0[1], bVl + (nd + li) * 136 + kin + lm * 8);
                mma_bf16(acc[nt], pa_h, bh0);
                mma_bf16(acc[nt], pa_h, bl0);
                mma_bf16(acc[nt], pa_l, bh0);
            }
            __syncthreads();
            if (t + 2 < 16) prefetchV(t + 2);
        }
        __syncthreads();

        // partial[kg][q][d]
        #pragma unroll
        for (int nt = 0; nt < 4; ++nt) {
            int nd = dh2 + nt * 8 + 2 * tg;
            *(float2*)&partial[kg * 1024 + g * 64 + nd] =
                make_float2(acc[nt][0], acc[nt][1]);
            *(float2*)&partial[kg * 1024 + (g + 8) * 64 + nd] =
                make_float2(acc[nt][2], acc[nt][3]);
        }
    }
    __syncthreads();

    // ---- Reduce 8 key-subgroups, write g_O ----
    {
        int b_ = bh >> 4;
        int h_ = bh & 15;
        #pragma unroll
        for (int rep = 0; rep < 2; ++rep) {
            int o = tid + rep * 512;
            int q = o >> 6;
            int d = o & 63;
            float s = 0.f;
            #pragma unroll
            for (int kg = 0; kg < 8; ++kg)
                s += partial[kg * 1024 + o];
            O[((size_t)(b_ * SS + q0 + q)) * DD + h_ * DHH + d] = s;
        }
    }
}

extern "C" void kernel_launch(void* const* d_in, const int* in_sizes, int n_in,
                              void* d_out, int out_size)
{
    const float* q    = (const float*)d_in[0];
    const float* k    = (const float*)d_in[1];
    const float* v    = (const float*)d_in[2];
    const int*   mask = (const int*)  d_in[3];
    const float* Wq   = (const float*)d_in[4];
    const float* Wk   = (const float*)d_in[5];
    const float* Wv   = (const float*)d_in[6];
    const float* Wo   = (const float*)d_in[7];
    float* out = (float*)d_out;

    __nv_bfloat16 *qh, *ql, *kh, *kl, *vth, *vtl;
    float *go;
    cudaGetSymbolAddress((void**)&qh,  g_Qh);
    cudaGetSymbolAddress((void**)&ql,  g_Ql);
    cudaGetSymbolAddress((void**)&kh,  g_Kh);
    cudaGetSymbolAddress((void**)&kl,  g_Kl);
    cudaGetSymbolAddress((void**)&vth, g_Vth);
    cudaGetSymbolAddress((void**)&vtl, g_Vtl);
    cudaGetSymbolAddress((void**)&go,  g_O);

    dim3 blkG(256);
    dim3 gridG(DD / 64, MM / 128);              // (16, 32)

    gemm_tc<0><<<gridG, blkG>>>(q, Wq, qh, ql, nullptr);
    gemm_tc<0><<<gridG, blkG>>>(k, Wk, kh, kl, nullptr);
    gemm_tc<3><<<gridG, blkG>>>(v, Wv, vth, vtl, nullptr);

    const long out_elems = (long)BB * SS * DD;  // 4194304
    int write_attn = (out_size > out_elems) ? 1 : 0;
    float* attn_out = out + out_elems;

    cudaFuncSetAttribute(attn_kernel,
                         cudaFuncAttributeMaxDynamicSharedMemorySize,
                         SMEM_ATTN);
    dim3 gridA(SS / 16, BB * HH);               // (128, 32)
    attn_kernel<<<gridA, 512, SMEM_ATTN>>>(mask, attn_out, write_attn,
                                           qh, ql, kh, kl, vth, vtl, go);

    gemm_tc<1><<<gridG, blkG>>>(go, Wo, nullptr, nullptr, out);
}